// round 14
// baseline (speedup 1.0000x reference)
#include <cuda_runtime.h>
#include <cuda_fp16.h>
#include <cstdint>

// ==================== static fp16 scratch (no allocs allowed) ====================
__device__ __half g_A[8192 * 2048];   // [x | h_prev]  : [8192][2048]
__device__ __half g_B[4096 * 2048];   // [Wf;Wi;Wc;Wo] : [4096][2048]

// ==================== fused convert kernel ====================

__global__ void __launch_bounds__(256)
conv_all_kernel(const float* __restrict__ x, const float* __restrict__ h,
                const float* __restrict__ wf, const float* __restrict__ wi,
                const float* __restrict__ wc, const float* __restrict__ wo) {
    const int nqA = 8192 * 2048 / 4;
    const int nqB = 4096 * 2048 / 4;
    const int total = nqA + nqB;
    for (int i = blockIdx.x * blockDim.x + threadIdx.x; i < total;
         i += gridDim.x * blockDim.x) {
        if (i < nqA) {
            const int m = i >> 9;
            const int k = (i & 511) * 4;
            const float* src = (k < 1024) ? (x + (size_t)m * 1024 + k)
                                          : (h + (size_t)m * 1024 + (k - 1024));
            const float4 v = *(const float4*)src;
            __half2* d = (__half2*)(g_A + (size_t)m * 2048 + k);
            d[0] = __floats2half2_rn(v.x, v.y);
            d[1] = __floats2half2_rn(v.z, v.w);
        } else {
            const int j = i - nqA;
            const int row = j >> 9;
            const int k = (j & 511) * 4;
            const int gate = row >> 10;
            const int n = row & 1023;
            const float* w = (gate == 0) ? wf : (gate == 1) ? wi : (gate == 2) ? wc : wo;
            const float4 v = *(const float4*)(w + (size_t)n * 2048 + k);
            __half2* d = (__half2*)(g_B + (size_t)row * 2048 + k);
            d[0] = __floats2half2_rn(v.x, v.y);
            d[1] = __floats2half2_rn(v.z, v.w);
        }
    }
}

// ==================== mbarrier helpers ====================

#define MBARRIER_INIT(addr, count) \
    asm volatile("mbarrier.init.shared.b64 [%0], %1;" \
                 :: "r"((uint32_t)(addr)), "r"((uint32_t)(count)) : "memory")

#define MBARRIER_ARRIVE(addr) \
    asm volatile("mbarrier.arrive.shared.b64 _, [%0];" \
                 :: "r"((uint32_t)(addr)) : "memory")

#define CP_ASYNC_MBAR_ARRIVE_NOINC(addr) \
    asm volatile("cp.async.mbarrier.arrive.noinc.shared::cta.b64 [%0];" \
                 :: "r"((uint32_t)(addr)) : "memory")

#define MBARRIER_WAIT_PARITY(mbar_smem_addr, phase_parity) do { \
    uint32_t _mbar = (uint32_t)(mbar_smem_addr); \
    uint32_t _parity = (uint32_t)(phase_parity); \
    uint32_t _done; \
    asm volatile( \
        "{\n\t" \
        ".reg .pred p;\n\t" \
        "mbarrier.try_wait.parity.acquire.cta.shared::cta.b64 p, [%1], %2;\n\t" \
        "selp.b32 %0, 1, 0, p;\n\t" \
        "}" \
        : "=r"(_done) : "r"(_mbar), "r"(_parity) : "memory"); \
    if (!_done) { \
        asm volatile( \
            "{\n\t" \
            ".reg .pred P1;\n\t" \
            "WAIT_LOOP_%=:\n\t" \
            "mbarrier.try_wait.parity.acquire.cta.shared::cta.b64 P1, [%0], %1, 0x989680;\n\t" \
            "@P1 bra.uni WAIT_DONE_%=;\n\t" \
            "bra.uni WAIT_LOOP_%=;\n\t" \
            "WAIT_DONE_%=:\n\t" \
            "}" \
            :: "r"(_mbar), "r"(_parity) : "memory"); \
    } \
} while(0)

// ==================== main fused GEMM + LSTM kernel ====================

static constexpr int BM = 64;
static constexpr int BN = 64;
static constexpr int BK = 64;
static constexpr int STAGES = 2;
static constexpr int SA = 72;     // 64 + 8 pad halfs — conflict-free
static constexpr int SB = 72;
static constexpr int A_STAGE = BM * SA;          // 4608 halfs
static constexpr int B_STAGE = 4 * BN * SB;      // 18432 halfs
static constexpr int STAGE_HALFS = A_STAGE + B_STAGE;          // 23040
static constexpr int SM_BAR_FULL  = 0;
static constexpr int SM_BAR_EMPTY = 16;
static constexpr int SM_TILES = 128;
static constexpr int SMEM_BYTES = SM_TILES + STAGES * STAGE_HALFS * 2;  // 92288

__device__ __forceinline__ uint32_t smem_u32(const void* p) {
    uint32_t a;
    asm("{ .reg .u64 t; cvta.to.shared.u64 t, %1; cvt.u32.u64 %0, t; }"
        : "=r"(a) : "l"(p));
    return a;
}

// cp.async with compile-time shared-memory offset ("n" prints as literal)
template <int OFF>
__device__ __forceinline__ void cpa16_o(uint32_t dst_base, const void* src) {
    asm volatile("cp.async.cg.shared.global [%0+%2], [%1], 16;"
                 :: "r"(dst_base), "l"(src), "n"(OFF));
}

// ldmatrix.x4 with compile-time shared-memory offset
template <int OFF>
__device__ __forceinline__ void ldmatrix_x4_o(uint32_t* r, uint32_t base) {
    asm volatile("ldmatrix.sync.aligned.m8n8.x4.shared.b16 {%0,%1,%2,%3}, [%4+%5];"
                 : "=r"(r[0]), "=r"(r[1]), "=r"(r[2]), "=r"(r[3])
                 : "r"(base), "n"(OFF));
}

__device__ __forceinline__ void mma16816(float* d, const uint32_t* a,
                                         uint32_t b0, uint32_t b1) {
    asm volatile(
        "mma.sync.aligned.m16n8k16.row.col.f32.f16.f16.f32 "
        "{%0,%1,%2,%3}, {%4,%5,%6,%7}, {%8,%9}, {%0,%1,%2,%3};"
        : "+f"(d[0]), "+f"(d[1]), "+f"(d[2]), "+f"(d[3])
        : "r"(a[0]), "r"(a[1]), "r"(a[2]), "r"(a[3]), "r"(b0), "r"(b1));
}

__device__ __forceinline__ float tanh_fast(float x) {
    float y;
    asm("tanh.approx.f32 %0, %1;" : "=f"(y) : "f"(x));
    return y;
}
__device__ __forceinline__ float sigmoid_(float x) {
    return fmaf(0.5f, tanh_fast(0.5f * x), 0.5f);
}
__device__ __forceinline__ float tanh_(float x) { return tanh_fast(x); }

struct Frags {
    uint32_t a[2][4];
    uint32_t b[4][4];
};

__global__ void __launch_bounds__(256, 2)
lstm_gemm_kernel(const float* __restrict__ b_f, const float* __restrict__ b_i,
                 const float* __restrict__ b_c, const float* __restrict__ b_o,
                 const float* __restrict__ c_prev, float* __restrict__ out) {
    extern __shared__ char smem_raw[];
    const uint32_t sb = smem_u32(smem_raw);
    __half* As = (__half*)(smem_raw + SM_TILES);
    __half* Bs = As + STAGES * A_STAGE;
    const uint32_t smA = smem_u32(As);
    const uint32_t smB = smem_u32(Bs);

    const int tid = threadIdx.x;
    const int wid = tid >> 5;
    const int lane = tid & 31;
    const int g8 = lane >> 2;
    const int t4 = lane & 3;
    const int warp_m = wid >> 2;
    const int warp_n = wid & 3;

    const int m0 = blockIdx.x * BM;
    const int n0 = blockIdx.y * BN;

    if (tid == 0) {
#pragma unroll
        for (int s = 0; s < STAGES; s++) {
            MBARRIER_INIT(sb + SM_BAR_FULL + s * 8, 256);
            MBARRIER_INIT(sb + SM_BAR_EMPTY + s * 8, 256);
        }
    }
    __syncthreads();

    // cp.async base addresses (stage-0 layout; stage offset via template imm)
    const __half* a_src0[2];
    uint32_t a_dst0[2];
#pragma unroll
    for (int i = 0; i < 2; i++) {
        const int c = tid + i * 256;
        const int row = c >> 3, seg = c & 7;
        a_src0[i] = g_A + (size_t)(m0 + row) * 2048 + seg * 8;
        a_dst0[i] = smA + (uint32_t)(row * SA + seg * 8) * 2;
    }
    const __half* b_src0[8];
    uint32_t b_dst0[8];
#pragma unroll
    for (int i = 0; i < 8; i++) {
        const int c = tid + i * 256;
        const int row = c >> 3, seg = c & 7;
        const int gate = row >> 6, nl = row & 63;
        b_src0[i] = g_B + (size_t)(gate * 1024 + n0 + nl) * 2048 + seg * 8;
        b_dst0[i] = smB + (uint32_t)(row * SB + seg * 8) * 2;
    }

    float acc[4][2][2][4];
#pragma unroll
    for (int g = 0; g < 4; g++)
#pragma unroll
        for (int mt = 0; mt < 2; mt++)
#pragma unroll
            for (int nt = 0; nt < 2; nt++)
#pragma unroll
                for (int c = 0; c < 4; c++) acc[g][mt][nt][c] = 0.0f;

    // ldmatrix per-lane bases (stage 0; stage offset via template imm)
    const int laneA_row = lane & 15;
    const int laneA_col = (lane >> 4) * 8;
    const uint32_t a_lm_base =
        smA + (uint32_t)((warp_m * 32 + laneA_row) * SA + laneA_col) * 2;
    const int laneB_row = (lane & 7) + ((lane >> 4) & 1) * 8;
    const int laneB_col = ((lane >> 3) & 1) * 8;
    const uint32_t b_lm_base =
        smB + (uint32_t)((warp_n * 16 + laneB_row) * SB + laneB_col) * 2;

    // fill stage STAGE with K offset k0 (halfs)
    auto fill = [&]<int STAGE>(int k0) {
        constexpr int AOFF = STAGE * A_STAGE * 2;
        constexpr int BOFF = STAGE * B_STAGE * 2;
#pragma unroll
        for (int i = 0; i < 2; i++) cpa16_o<AOFF>(a_dst0[i], a_src0[i] + k0);
#pragma unroll
        for (int i = 0; i < 8; i++) cpa16_o<BOFF>(b_dst0[i], b_src0[i] + k0);
        CP_ASYNC_MBAR_ARRIVE_NOINC(sb + SM_BAR_FULL + STAGE * 8);
    };

    // load fragments from stage STAGE at K-slot KS (halfs)
    auto load_frags = [&]<int STAGE, int KS>(Frags& f) {
        constexpr int AO = STAGE * A_STAGE * 2 + KS * 2;
        constexpr int BO = STAGE * B_STAGE * 2 + KS * 2;
        ldmatrix_x4_o<AO>(f.a[0], a_lm_base);
        ldmatrix_x4_o<AO + 16 * SA * 2>(f.a[1], a_lm_base);
        ldmatrix_x4_o<BO + 0 * 64 * SB * 2>(f.b[0], b_lm_base);
        ldmatrix_x4_o<BO + 1 * 64 * SB * 2>(f.b[1], b_lm_base);
        ldmatrix_x4_o<BO + 2 * 64 * SB * 2>(f.b[2], b_lm_base);
        ldmatrix_x4_o<BO + 3 * 64 * SB * 2>(f.b[3], b_lm_base);
    };

    auto mma_burst = [&](const Frags& f) {
#pragma unroll
        for (int g = 0; g < 4; g++) {
#pragma unroll
            for (int mt = 0; mt < 2; mt++) {
                mma16816(acc[g][mt][0], f.a[mt], f.b[g][0], f.b[g][1]);
                mma16816(acc[g][mt][1], f.a[mt], f.b[g][2], f.b[g][3]);
            }
        }
    };

    // ---- prologue ----
    fill.template operator()<0>(0);
    fill.template operator()<1>(BK);

    MBARRIER_WAIT_PARITY(sb + SM_BAR_FULL + 0, 0);
    Frags F0, F1;
    load_frags.template operator()<0, 0>(F0);

    const int NKT2 = 16;   // 32 kt, processed as even/odd pairs
    for (int j = 0; j < NKT2; j++) {
        const int pj = j & 1;

        // ---- even kt: stage 0 ----
        load_frags.template operator()<0, 16>(F1);
        mma_burst(F0);
        load_frags.template operator()<0, 32>(F0);
        mma_burst(F1);
        load_frags.template operator()<0, 48>(F1);
        mma_burst(F0);
        MBARRIER_ARRIVE(sb + SM_BAR_EMPTY + 0);

        MBARRIER_WAIT_PARITY(sb + SM_BAR_FULL + 8, pj);   // full[1], cons idx j
        load_frags.template operator()<1, 0>(F0);
        mma_burst(F1);

        if (j < NKT2 - 1) {
            MBARRIER_WAIT_PARITY(sb + SM_BAR_EMPTY + 0, pj);
            fill.template operator()<0>((2 * j + 2) * BK);
        }

        // ---- odd kt: stage 1 ----
        load_frags.template operator()<1, 16>(F1);
        mma_burst(F0);
        load_frags.template operator()<1, 32>(F0);
        mma_burst(F1);
        load_frags.template operator()<1, 48>(F1);
        mma_burst(F0);
        MBARRIER_ARRIVE(sb + SM_BAR_EMPTY + 8);

        if (j < NKT2 - 1) {
            MBARRIER_WAIT_PARITY(sb + SM_BAR_FULL + 0, pj ^ 1);  // full[0], cons idx j+1
            load_frags.template operator()<0, 0>(F0);
        }
        mma_burst(F1);

        if (j < NKT2 - 1) {
            MBARRIER_WAIT_PARITY(sb + SM_BAR_EMPTY + 8, pj);
            fill.template operator()<1>((2 * j + 3) * BK);
        }
    }

    // ---- fused LSTM epilogue ----
    float* h_out = out;
    float* c_out = out + (size_t)8192 * 1024;

#pragma unroll
    for (int mt = 0; mt < 2; mt++) {
#pragma unroll
        for (int nt = 0; nt < 2; nt++) {
            const int n = n0 + warp_n * 16 + nt * 8 + 2 * t4;
            const float2 bf = *(const float2*)(b_f + n);
            const float2 bi = *(const float2*)(b_i + n);
            const float2 bc = *(const float2*)(b_c + n);
            const float2 bo = *(const float2*)(b_o + n);
#pragma unroll
            for (int rr = 0; rr < 2; rr++) {
                const int m = m0 + warp_m * 32 + mt * 16 + g8 + rr * 8;
                const float2 cp = *(const float2*)(c_prev + (size_t)m * 1024 + n);
                const int i0 = rr * 2, i1 = rr * 2 + 1;

                float2 hv, cv;
                {
                    const float ft = sigmoid_(acc[0][mt][nt][i0] + bf.x);
                    const float it = sigmoid_(acc[1][mt][nt][i0] + bi.x);
                    const float ct = tanh_(acc[2][mt][nt][i0] + bc.x);
                    const float ot = sigmoid_(acc[3][mt][nt][i0] + bo.x);
                    cv.x = ft * cp.x + it * ct;
                    hv.x = ot * tanh_(cv.x);
                }
                {
                    const float ft = sigmoid_(acc[0][mt][nt][i1] + bf.y);
                    const float it = sigmoid_(acc[1][mt][nt][i1] + bi.y);
                    const float ct = tanh_(acc[2][mt][nt][i1] + bc.y);
                    const float ot = sigmoid_(acc[3][mt][nt][i1] + bo.y);
                    cv.y = ft * cp.y + it * ct;
                    hv.y = ot * tanh_(cv.y);
                }
                *(float2*)(h_out + (size_t)m * 1024 + n) = hv;
                *(float2*)(c_out + (size_t)m * 1024 + n) = cv;
            }
        }
    }
}

// ==================== host side ====================

extern "C" void kernel_launch(void* const* d_in, const int* in_sizes, int n_in,
                              void* d_out, int out_size) {
    const float* x      = (const float*)d_in[0];
    const float* h_prev = (const float*)d_in[1];
    const float* c_prev = (const float*)d_in[2];
    const float* W_f = (const float*)d_in[3];
    const float* b_f = (const float*)d_in[4];
    const float* W_i = (const float*)d_in[5];
    const float* b_i = (const float*)d_in[6];
    const float* W_c = (const float*)d_in[7];
    const float* b_c = (const float*)d_in[8];
    const float* W_o = (const float*)d_in[9];
    const float* b_o = (const float*)d_in[10];
    float* out = (float*)d_out;

    cudaFuncSetAttribute(lstm_gemm_kernel,
                         cudaFuncAttributeMaxDynamicSharedMemorySize, SMEM_BYTES);

    conv_all_kernel<<<3072, 256>>>(x, h_prev, W_f, W_i, W_c, W_o);

    dim3 grid(8192 / BM, 1024 / BN);   // (128, 16)
    lstm_gemm_kernel<<<grid, 256, SMEM_BYTES>>>(b_f, b_i, b_c, b_o, c_prev, out);
}

// round 15
// speedup vs baseline: 1.1011x; 1.1011x over previous
#include <cuda_runtime.h>
#include <cuda_fp16.h>
#include <cstdint>

// ==================== static fp16 scratch (no allocs allowed) ====================
__device__ __half g_A[8192 * 2048];   // [x | h_prev]  : [8192][2048]
__device__ __half g_B[4096 * 2048];   // [Wf;Wi;Wc;Wo] : [4096][2048]

// ==================== fused convert kernel ====================

__global__ void __launch_bounds__(256)
conv_all_kernel(const float* __restrict__ x, const float* __restrict__ h,
                const float* __restrict__ wf, const float* __restrict__ wi,
                const float* __restrict__ wc, const float* __restrict__ wo) {
    const int nqA = 8192 * 2048 / 4;
    const int nqB = 4096 * 2048 / 4;
    const int total = nqA + nqB;
    for (int i = blockIdx.x * blockDim.x + threadIdx.x; i < total;
         i += gridDim.x * blockDim.x) {
        if (i < nqA) {
            const int m = i >> 9;
            const int k = (i & 511) * 4;
            const float* src = (k < 1024) ? (x + (size_t)m * 1024 + k)
                                          : (h + (size_t)m * 1024 + (k - 1024));
            const float4 v = *(const float4*)src;
            __half2* d = (__half2*)(g_A + (size_t)m * 2048 + k);
            d[0] = __floats2half2_rn(v.x, v.y);
            d[1] = __floats2half2_rn(v.z, v.w);
        } else {
            const int j = i - nqA;
            const int row = j >> 9;
            const int k = (j & 511) * 4;
            const int gate = row >> 10;
            const int n = row & 1023;
            const float* w = (gate == 0) ? wf : (gate == 1) ? wi : (gate == 2) ? wc : wo;
            const float4 v = *(const float4*)(w + (size_t)n * 2048 + k);
            __half2* d = (__half2*)(g_B + (size_t)row * 2048 + k);
            d[0] = __floats2half2_rn(v.x, v.y);
            d[1] = __floats2half2_rn(v.z, v.w);
        }
    }
}

// ==================== mbarrier helpers ====================

#define MBARRIER_INIT(addr, count) \
    asm volatile("mbarrier.init.shared.b64 [%0], %1;" \
                 :: "r"((uint32_t)(addr)), "r"((uint32_t)(count)) : "memory")

#define MBARRIER_ARRIVE(addr) \
    asm volatile("mbarrier.arrive.shared.b64 _, [%0];" \
                 :: "r"((uint32_t)(addr)) : "memory")

#define CP_ASYNC_MBAR_ARRIVE_NOINC(addr) \
    asm volatile("cp.async.mbarrier.arrive.noinc.shared::cta.b64 [%0];" \
                 :: "r"((uint32_t)(addr)) : "memory")

#define MBARRIER_WAIT_PARITY(mbar_smem_addr, phase_parity) do { \
    uint32_t _mbar = (uint32_t)(mbar_smem_addr); \
    uint32_t _parity = (uint32_t)(phase_parity); \
    uint32_t _done; \
    asm volatile( \
        "{\n\t" \
        ".reg .pred p;\n\t" \
        "mbarrier.try_wait.parity.acquire.cta.shared::cta.b64 p, [%1], %2;\n\t" \
        "selp.b32 %0, 1, 0, p;\n\t" \
        "}" \
        : "=r"(_done) : "r"(_mbar), "r"(_parity) : "memory"); \
    if (!_done) { \
        asm volatile( \
            "{\n\t" \
            ".reg .pred P1;\n\t" \
            "WAIT_LOOP_%=:\n\t" \
            "mbarrier.try_wait.parity.acquire.cta.shared::cta.b64 P1, [%0], %1, 0x989680;\n\t" \
            "@P1 bra.uni WAIT_DONE_%=;\n\t" \
            "bra.uni WAIT_LOOP_%=;\n\t" \
            "WAIT_DONE_%=:\n\t" \
            "}" \
            :: "r"(_mbar), "r"(_parity) : "memory"); \
    } \
} while(0)

// ==================== main fused GEMM + LSTM kernel ====================

static constexpr int BM = 64;
static constexpr int BN = 64;
static constexpr int BK = 64;     // 2 stages, low wait frequency (R12 structure)
static constexpr int STAGES = 2;
static constexpr int SA = 72;     // 64 + 8 pad halfs — conflict-free
static constexpr int SB = 72;
static constexpr int A_STAGE = BM * SA;          // 4608 halfs
static constexpr int B_STAGE = 4 * BN * SB;      // 18432 halfs
static constexpr int STAGE_HALFS = A_STAGE + B_STAGE;          // 23040
static constexpr int SM_BAR_FULL  = 0;    // full[s]  = s*8
static constexpr int SM_BAR_EMPTY = 16;   // empty[s] = 16 + s*8
static constexpr int SM_TILES = 128;
static constexpr int SMEM_BYTES = SM_TILES + STAGES * STAGE_HALFS * 2;  // 92288

__device__ __forceinline__ uint32_t smem_u32(const void* p) {
    uint32_t a;
    asm("{ .reg .u64 t; cvta.to.shared.u64 t, %1; cvt.u32.u64 %0, t; }"
        : "=r"(a) : "l"(p));
    return a;
}

__device__ __forceinline__ void cpa16(uint32_t dst, const void* src) {
    asm volatile("cp.async.cg.shared.global [%0], [%1], 16;" :: "r"(dst), "l"(src));
}

__device__ __forceinline__ void ldmatrix_x4(uint32_t* r, uint32_t addr) {
    asm volatile("ldmatrix.sync.aligned.m8n8.x4.shared.b16 {%0,%1,%2,%3}, [%4];"
                 : "=r"(r[0]), "=r"(r[1]), "=r"(r[2]), "=r"(r[3]) : "r"(addr));
}

__device__ __forceinline__ void mma16816(float* d, const uint32_t* a,
                                         uint32_t b0, uint32_t b1) {
    asm volatile(
        "mma.sync.aligned.m16n8k16.row.col.f32.f16.f16.f32 "
        "{%0,%1,%2,%3}, {%4,%5,%6,%7}, {%8,%9}, {%0,%1,%2,%3};"
        : "+f"(d[0]), "+f"(d[1]), "+f"(d[2]), "+f"(d[3])
        : "r"(a[0]), "r"(a[1]), "r"(a[2]), "r"(a[3]), "r"(b0), "r"(b1));
}

// tanh.approx epilogue: accuracy verified in R14 (rel_err 1.7054e-4 vs 1.7046e-4 exact)
__device__ __forceinline__ float tanh_fast(float x) {
    float y;
    asm("tanh.approx.f32 %0, %1;" : "=f"(y) : "f"(x));
    return y;
}
__device__ __forceinline__ float sigmoid_(float x) {
    return fmaf(0.5f, tanh_fast(0.5f * x), 0.5f);
}
__device__ __forceinline__ float tanh_(float x) { return tanh_fast(x); }

struct Frags {
    uint32_t a[2][4];
    uint32_t b[4][4];
};

__global__ void __launch_bounds__(256, 2)
lstm_gemm_kernel(const float* __restrict__ b_f, const float* __restrict__ b_i,
                 const float* __restrict__ b_c, const float* __restrict__ b_o,
                 const float* __restrict__ c_prev, float* __restrict__ out) {
    extern __shared__ char smem_raw[];
    const uint32_t sb = smem_u32(smem_raw);
    __half* As = (__half*)(smem_raw + SM_TILES);           // [STAGES][BM][SA]
    __half* Bs = As + STAGES * A_STAGE;                    // [STAGES][4*BN][SB]
    const uint32_t smA = smem_u32(As);
    const uint32_t smB = smem_u32(Bs);

    const int tid = threadIdx.x;
    const int wid = tid >> 5;
    const int lane = tid & 31;
    const int g8 = lane >> 2;
    const int t4 = lane & 3;
    const int warp_m = wid >> 2;   // 0..1
    const int warp_n = wid & 3;    // 0..3

    const int m0 = blockIdx.x * BM;
    const int n0 = blockIdx.y * BN;

    if (tid == 0) {
#pragma unroll
        for (int s = 0; s < STAGES; s++) {
            MBARRIER_INIT(sb + SM_BAR_FULL + s * 8, 256);
            MBARRIER_INIT(sb + SM_BAR_EMPTY + s * 8, 256);
        }
    }
    __syncthreads();

    // cp.async addressing — A: 512 chunks (2/thread); B: 2048 chunks (8/thread)
    const __half* a_src0[2];
    uint32_t a_dst0[2];
#pragma unroll
    for (int i = 0; i < 2; i++) {
        const int c = tid + i * 256;
        const int row = c >> 3, seg = c & 7;
        a_src0[i] = g_A + (size_t)(m0 + row) * 2048 + seg * 8;
        a_dst0[i] = smA + (uint32_t)(row * SA + seg * 8) * 2;
    }
    const __half* b_src0[8];
    uint32_t b_dst0[8];
#pragma unroll
    for (int i = 0; i < 8; i++) {
        const int c = tid + i * 256;
        const int row = c >> 3, seg = c & 7;
        const int gate = row >> 6, nl = row & 63;
        b_src0[i] = g_B + (size_t)(gate * 1024 + n0 + nl) * 2048 + seg * 8;
        b_dst0[i] = smB + (uint32_t)(row * SB + seg * 8) * 2;
    }

    float acc[4][2][2][4];
#pragma unroll
    for (int g = 0; g < 4; g++)
#pragma unroll
        for (int mt = 0; mt < 2; mt++)
#pragma unroll
            for (int nt = 0; nt < 2; nt++)
#pragma unroll
                for (int c = 0; c < 4; c++) acc[g][mt][nt][c] = 0.0f;

    // ldmatrix per-lane bases
    const int laneA_row = lane & 15;
    const int laneA_col = (lane >> 4) * 8;
    const uint32_t a_lm_base =
        smA + (uint32_t)((warp_m * 32 + laneA_row) * SA + laneA_col) * 2;
    const int laneB_row = (lane & 7) + ((lane >> 4) & 1) * 8;
    const int laneB_col = ((lane >> 3) & 1) * 8;
    const uint32_t b_lm_base =
        smB + (uint32_t)((warp_n * 16 + laneB_row) * SB + laneB_col) * 2;

    auto fill_stage = [&](int stage, int k0) {
#pragma unroll
        for (int i = 0; i < 2; i++)
            cpa16(a_dst0[i] + stage * A_STAGE * 2, a_src0[i] + k0);
#pragma unroll
        for (int i = 0; i < 8; i++)
            cpa16(b_dst0[i] + stage * B_STAGE * 2, b_src0[i] + k0);
        CP_ASYNC_MBAR_ARRIVE_NOINC(sb + SM_BAR_FULL + stage * 8);
    };

    auto load_frags = [&](Frags& f, int stage, int ks) {
        const uint32_t aS = a_lm_base + stage * A_STAGE * 2;
        const uint32_t bS = b_lm_base + stage * B_STAGE * 2;
        ldmatrix_x4(f.a[0], aS + (uint32_t)(ks) * 2);
        ldmatrix_x4(f.a[1], aS + (uint32_t)(16 * SA + ks) * 2);
#pragma unroll
        for (int g = 0; g < 4; g++)
            ldmatrix_x4(f.b[g], bS + (uint32_t)(g * 64 * SB + ks) * 2);
    };

    auto mma_burst = [&](const Frags& f) {
#pragma unroll
        for (int g = 0; g < 4; g++) {
#pragma unroll
            for (int mt = 0; mt < 2; mt++) {
                mma16816(acc[g][mt][0], f.a[mt], f.b[g][0], f.b[g][1]);
                mma16816(acc[g][mt][1], f.a[mt], f.b[g][2], f.b[g][3]);
            }
        }
    };

    const int NKT = 2048 / BK;   // 32

    // ---- prologue: fill both stages ----
    fill_stage(0, 0);
    fill_stage(1, BK);

    MBARRIER_WAIT_PARITY(sb + SM_BAR_FULL + 0, 0);
    Frags F0, F1;
    load_frags(F0, 0, 0);

    for (int kt = 0; kt < NKT; kt++) {
        const int s = kt & 1;
        const int s1 = s ^ 1;

        load_frags(F1, s, 16);
        mma_burst(F0);                   // (s, 0)
        load_frags(F0, s, 32);
        mma_burst(F1);                   // (s, 16)
        load_frags(F1, s, 48);           // last read of stage s
        mma_burst(F0);                   // (s, 32)
        MBARRIER_ARRIVE(sb + SM_BAR_EMPTY + s * 8);   // all reads of stage s done

        if (kt < NKT - 1) {
            const int par_full = ((kt + 1) >> 1) & 1;     // consumption idx of s1
            MBARRIER_WAIT_PARITY(sb + SM_BAR_FULL + s1 * 8, par_full);
            load_frags(F0, s1, 0);       // lead-in for next kt
        }
        mma_burst(F1);                   // (s, 48)

        if (kt < NKT - 2) {
            const int par_empty = (kt >> 1) & 1;          // this kt's phase of empty[s]
            MBARRIER_WAIT_PARITY(sb + SM_BAR_EMPTY + s * 8, par_empty);
            fill_stage(s, (kt + 2) * BK);
        }
    }

    // ---- fused LSTM epilogue (warp-private accumulators; no sync needed) ----
    float* h_out = out;
    float* c_out = out + (size_t)8192 * 1024;

#pragma unroll
    for (int mt = 0; mt < 2; mt++) {
#pragma unroll
        for (int nt = 0; nt < 2; nt++) {
            const int n = n0 + warp_n * 16 + nt * 8 + 2 * t4;
            const float2 bf = *(const float2*)(b_f + n);
            const float2 bi = *(const float2*)(b_i + n);
            const float2 bc = *(const float2*)(b_c + n);
            const float2 bo = *(const float2*)(b_o + n);
#pragma unroll
            for (int rr = 0; rr < 2; rr++) {
                const int m = m0 + warp_m * 32 + mt * 16 + g8 + rr * 8;
                const float2 cp = *(const float2*)(c_prev + (size_t)m * 1024 + n);
                const int i0 = rr * 2, i1 = rr * 2 + 1;

                float2 hv, cv;
                {
                    const float ft = sigmoid_(acc[0][mt][nt][i0] + bf.x);
                    const float it = sigmoid_(acc[1][mt][nt][i0] + bi.x);
                    const float ct = tanh_(acc[2][mt][nt][i0] + bc.x);
                    const float ot = sigmoid_(acc[3][mt][nt][i0] + bo.x);
                    cv.x = ft * cp.x + it * ct;
                    hv.x = ot * tanh_(cv.x);
                }
                {
                    const float ft = sigmoid_(acc[0][mt][nt][i1] + bf.y);
                    const float it = sigmoid_(acc[1][mt][nt][i1] + bi.y);
                    const float ct = tanh_(acc[2][mt][nt][i1] + bc.y);
                    const float ot = sigmoid_(acc[3][mt][nt][i1] + bo.y);
                    cv.y = ft * cp.y + it * ct;
                    hv.y = ot * tanh_(cv.y);
                }
                *(float2*)(h_out + (size_t)m * 1024 + n) = hv;
                *(float2*)(c_out + (size_t)m * 1024 + n) = cv;
            }
        }
    }
}

// ==================== host side ====================

extern "C" void kernel_launch(void* const* d_in, const int* in_sizes, int n_in,
                              void* d_out, int out_size) {
    const float* x      = (const float*)d_in[0];
    const float* h_prev = (const float*)d_in[1];
    const float* c_prev = (const float*)d_in[2];
    const float* W_f = (const float*)d_in[3];
    const float* b_f = (const float*)d_in[4];
    const float* W_i = (const float*)d_in[5];
    const float* b_i = (const float*)d_in[6];
    const float* W_c = (const float*)d_in[7];
    const float* b_c = (const float*)d_in[8];
    const float* W_o = (const float*)d_in[9];
    const float* b_o = (const float*)d_in[10];
    float* out = (float*)d_out;

    cudaFuncSetAttribute(lstm_gemm_kernel,
                         cudaFuncAttributeMaxDynamicSharedMemorySize, SMEM_BYTES);

    conv_all_kernel<<<3072, 256>>>(x, h_prev, W_f, W_i, W_c, W_o);

    dim3 grid(8192 / BM, 1024 / BN);   // (128, 16)
    lstm_gemm_kernel<<<grid, 256, SMEM_BYTES>>>(b_f, b_i, b_c, b_o, c_prev, out);
}

// round 17
// speedup vs baseline: 1.1171x; 1.0146x over previous
#include <cuda_runtime.h>
#include <cuda_fp16.h>
#include <cstdint>

// ==================== static fp16 scratch (no allocs allowed) ====================
__device__ __half g_A[8192 * 2048];   // [x | h_prev]  : [8192][2048]
__device__ __half g_B[4096 * 2048];   // [Wf;Wi;Wc;Wo] : [4096][2048]

// ==================== fused convert kernel (8 halfs / thread / iter) ====================

__device__ __forceinline__ void conv8(const float* __restrict__ src, __half* __restrict__ dst) {
    const float4 v0 = *(const float4*)src;
    const float4 v1 = *(const float4*)(src + 4);
    __half2 h[4];
    h[0] = __floats2half2_rn(v0.x, v0.y);
    h[1] = __floats2half2_rn(v0.z, v0.w);
    h[2] = __floats2half2_rn(v1.x, v1.y);
    h[3] = __floats2half2_rn(v1.z, v1.w);
    *(uint4*)dst = *(const uint4*)h;
}

__global__ void __launch_bounds__(256)
conv_all_kernel(const float* __restrict__ x, const float* __restrict__ h,
                const float* __restrict__ wf, const float* __restrict__ wi,
                const float* __restrict__ wc, const float* __restrict__ wo) {
    const int n8A = 8192 * 2048 / 8;   // 2M chunks of 8 halfs
    const int n8B = 4096 * 2048 / 8;   // 1M chunks
    const int total = n8A + n8B;
    for (int i = blockIdx.x * blockDim.x + threadIdx.x; i < total;
         i += gridDim.x * blockDim.x) {
        if (i < n8A) {
            const int m = i >> 8;              // 256 chunks per 2048-row
            const int k = (i & 255) * 8;       // 8-half chunk; never straddles 1024
            const float* src = (k < 1024) ? (x + (size_t)m * 1024 + k)
                                          : (h + (size_t)m * 1024 + (k - 1024));
            conv8(src, g_A + (size_t)m * 2048 + k);
        } else {
            const int j = i - n8A;
            const int row = j >> 8;            // 0..4095
            const int k = (j & 255) * 8;
            const int gate = row >> 10;
            const int n = row & 1023;
            const float* w = (gate == 0) ? wf : (gate == 1) ? wi : (gate == 2) ? wc : wo;
            conv8(w + (size_t)n * 2048 + k, g_B + (size_t)row * 2048 + k);
        }
    }
}

// ==================== mbarrier helpers ====================

#define MBARRIER_INIT(addr, count) \
    asm volatile("mbarrier.init.shared.b64 [%0], %1;" \
                 :: "r"((uint32_t)(addr)), "r"((uint32_t)(count)) : "memory")

#define MBARRIER_ARRIVE(addr) \
    asm volatile("mbarrier.arrive.shared.b64 _, [%0];" \
                 :: "r"((uint32_t)(addr)) : "memory")

#define CP_ASYNC_MBAR_ARRIVE_NOINC(addr) \
    asm volatile("cp.async.mbarrier.arrive.noinc.shared::cta.b64 [%0];" \
                 :: "r"((uint32_t)(addr)) : "memory")

#define MBARRIER_WAIT_PARITY(mbar_smem_addr, phase_parity) do { \
    uint32_t _mbar = (uint32_t)(mbar_smem_addr); \
    uint32_t _parity = (uint32_t)(phase_parity); \
    uint32_t _done; \
    asm volatile( \
        "{\n\t" \
        ".reg .pred p;\n\t" \
        "mbarrier.try_wait.parity.acquire.cta.shared::cta.b64 p, [%1], %2;\n\t" \
        "selp.b32 %0, 1, 0, p;\n\t" \
        "}" \
        : "=r"(_done) : "r"(_mbar), "r"(_parity) : "memory"); \
    if (!_done) { \
        asm volatile( \
            "{\n\t" \
            ".reg .pred P1;\n\t" \
            "WAIT_LOOP_%=:\n\t" \
            "mbarrier.try_wait.parity.acquire.cta.shared::cta.b64 P1, [%0], %1, 0x989680;\n\t" \
            "@P1 bra.uni WAIT_DONE_%=;\n\t" \
            "bra.uni WAIT_LOOP_%=;\n\t" \
            "WAIT_DONE_%=:\n\t" \
            "}" \
            :: "r"(_mbar), "r"(_parity) : "memory"); \
    } \
} while(0)

// ==================== main fused GEMM + LSTM kernel (R15, unchanged) ====================

static constexpr int BM = 64;
static constexpr int BN = 64;
static constexpr int BK = 64;
static constexpr int STAGES = 2;
static constexpr int SA = 72;
static constexpr int SB = 72;
static constexpr int A_STAGE = BM * SA;          // 4608 halfs
static constexpr int B_STAGE = 4 * BN * SB;      // 18432 halfs
static constexpr int STAGE_HALFS = A_STAGE + B_STAGE;          // 23040
static constexpr int SM_BAR_FULL  = 0;
static constexpr int SM_BAR_EMPTY = 16;
static constexpr int SM_TILES = 128;
static constexpr int SMEM_BYTES = SM_TILES + STAGES * STAGE_HALFS * 2;  // 92288

__device__ __forceinline__ uint32_t smem_u32(const void* p) {
    uint32_t a;
    asm("{ .reg .u64 t; cvta.to.shared.u64 t, %1; cvt.u32.u64 %0, t; }"
        : "=r"(a) : "l"(p));
    return a;
}

__device__ __forceinline__ void cpa16(uint32_t dst, const void* src) {
    asm volatile("cp.async.cg.shared.global [%0], [%1], 16;" :: "r"(dst), "l"(src));
}

__device__ __forceinline__ void ldmatrix_x4(uint32_t* r, uint32_t addr) {
    asm volatile("ldmatrix.sync.aligned.m8n8.x4.shared.b16 {%0,%1,%2,%3}, [%4];"
                 : "=r"(r[0]), "=r"(r[1]), "=r"(r[2]), "=r"(r[3]) : "r"(addr));
}

__device__ __forceinline__ void mma16816(float* d, const uint32_t* a,
                                         uint32_t b0, uint32_t b1) {
    asm volatile(
        "mma.sync.aligned.m16n8k16.row.col.f32.f16.f16.f32 "
        "{%0,%1,%2,%3}, {%4,%5,%6,%7}, {%8,%9}, {%0,%1,%2,%3};"
        : "+f"(d[0]), "+f"(d[1]), "+f"(d[2]), "+f"(d[3])
        : "r"(a[0]), "r"(a[1]), "r"(a[2]), "r"(a[3]), "r"(b0), "r"(b1));
}

// tanh.approx epilogue: accuracy verified (rel_err 1.7054e-4 vs 1.7046e-4 exact)
__device__ __forceinline__ float tanh_fast(float x) {
    float y;
    asm("tanh.approx.f32 %0, %1;" : "=f"(y) : "f"(x));
    return y;
}
__device__ __forceinline__ float sigmoid_(float x) {
    return fmaf(0.5f, tanh_fast(0.5f * x), 0.5f);
}
__device__ __forceinline__ float tanh_(float x) { return tanh_fast(x); }

struct Frags {
    uint32_t a[2][4];
    uint32_t b[4][4];
};

__global__ void __launch_bounds__(256, 2)
lstm_gemm_kernel(const float* __restrict__ b_f, const float* __restrict__ b_i,
                 const float* __restrict__ b_c, const float* __restrict__ b_o,
                 const float* __restrict__ c_prev, float* __restrict__ out) {
    extern __shared__ char smem_raw[];
    const uint32_t sb = smem_u32(smem_raw);
    __half* As = (__half*)(smem_raw + SM_TILES);           // [STAGES][BM][SA]
    __half* Bs = As + STAGES * A_STAGE;                    // [STAGES][4*BN][SB]
    const uint32_t smA = smem_u32(As);
    const uint32_t smB = smem_u32(Bs);

    const int tid = threadIdx.x;
    const int wid = tid >> 5;
    const int lane = tid & 31;
    const int g8 = lane >> 2;
    const int t4 = lane & 3;
    const int warp_m = wid >> 2;   // 0..1
    const int warp_n = wid & 3;    // 0..3

    const int m0 = blockIdx.x * BM;
    const int n0 = blockIdx.y * BN;

    if (tid == 0) {
#pragma unroll
        for (int s = 0; s < STAGES; s++) {
            MBARRIER_INIT(sb + SM_BAR_FULL + s * 8, 256);
            MBARRIER_INIT(sb + SM_BAR_EMPTY + s * 8, 256);
        }
    }
    __syncthreads();

    // cp.async addressing — A: 512 chunks (2/thread); B: 2048 chunks (8/thread)
    const __half* a_src0[2];
    uint32_t a_dst0[2];
#pragma unroll
    for (int i = 0; i < 2; i++) {
        const int c = tid + i * 256;
        const int row = c >> 3, seg = c & 7;
        a_src0[i] = g_A + (size_t)(m0 + row) * 2048 + seg * 8;
        a_dst0[i] = smA + (uint32_t)(row * SA + seg * 8) * 2;
    }
    const __half* b_src0[8];
    uint32_t b_dst0[8];
#pragma unroll
    for (int i = 0; i < 8; i++) {
        const int c = tid + i * 256;
        const int row = c >> 3, seg = c & 7;
        const int gate = row >> 6, nl = row & 63;
        b_src0[i] = g_B + (size_t)(gate * 1024 + n0 + nl) * 2048 + seg * 8;
        b_dst0[i] = smB + (uint32_t)(row * SB + seg * 8) * 2;
    }

    float acc[4][2][2][4];
#pragma unroll
    for (int g = 0; g < 4; g++)
#pragma unroll
        for (int mt = 0; mt < 2; mt++)
#pragma unroll
            for (int nt = 0; nt < 2; nt++)
#pragma unroll
                for (int c = 0; c < 4; c++) acc[g][mt][nt][c] = 0.0f;

    // ldmatrix per-lane bases
    const int laneA_row = lane & 15;
    const int laneA_col = (lane >> 4) * 8;
    const uint32_t a_lm_base =
        smA + (uint32_t)((warp_m * 32 + laneA_row) * SA + laneA_col) * 2;
    const int laneB_row = (lane & 7) + ((lane >> 4) & 1) * 8;
    const int laneB_col = ((lane >> 3) & 1) * 8;
    const uint32_t b_lm_base =
        smB + (uint32_t)((warp_n * 16 + laneB_row) * SB + laneB_col) * 2;

    auto fill_stage = [&](int stage, int k0) {
#pragma unroll
        for (int i = 0; i < 2; i++)
            cpa16(a_dst0[i] + stage * A_STAGE * 2, a_src0[i] + k0);
#pragma unroll
        for (int i = 0; i < 8; i++)
            cpa16(b_dst0[i] + stage * B_STAGE * 2, b_src0[i] + k0);
        CP_ASYNC_MBAR_ARRIVE_NOINC(sb + SM_BAR_FULL + stage * 8);
    };

    auto load_frags = [&](Frags& f, int stage, int ks) {
        const uint32_t aS = a_lm_base + stage * A_STAGE * 2;
        const uint32_t bS = b_lm_base + stage * B_STAGE * 2;
        ldmatrix_x4(f.a[0], aS + (uint32_t)(ks) * 2);
        ldmatrix_x4(f.a[1], aS + (uint32_t)(16 * SA + ks) * 2);
#pragma unroll
        for (int g = 0; g < 4; g++)
            ldmatrix_x4(f.b[g], bS + (uint32_t)(g * 64 * SB + ks) * 2);
    };

    auto mma_burst = [&](const Frags& f) {
#pragma unroll
        for (int g = 0; g < 4; g++) {
#pragma unroll
            for (int mt = 0; mt < 2; mt++) {
                mma16816(acc[g][mt][0], f.a[mt], f.b[g][0], f.b[g][1]);
                mma16816(acc[g][mt][1], f.a[mt], f.b[g][2], f.b[g][3]);
            }
        }
    };

    const int NKT = 2048 / BK;   // 32

    // ---- prologue: fill both stages ----
    fill_stage(0, 0);
    fill_stage(1, BK);

    MBARRIER_WAIT_PARITY(sb + SM_BAR_FULL + 0, 0);
    Frags F0, F1;
    load_frags(F0, 0, 0);

    for (int kt = 0; kt < NKT; kt++) {
        const int s = kt & 1;
        const int s1 = s ^ 1;

        load_frags(F1, s, 16);
        mma_burst(F0);                   // (s, 0)
        load_frags(F0, s, 32);
        mma_burst(F1);                   // (s, 16)
        load_frags(F1, s, 48);           // last read of stage s
        mma_burst(F0);                   // (s, 32)
        MBARRIER_ARRIVE(sb + SM_BAR_EMPTY + s * 8);   // all reads of stage s done

        if (kt < NKT - 1) {
            const int par_full = ((kt + 1) >> 1) & 1;     // consumption idx of s1
            MBARRIER_WAIT_PARITY(sb + SM_BAR_FULL + s1 * 8, par_full);
            load_frags(F0, s1, 0);       // lead-in for next kt
        }
        mma_burst(F1);                   // (s, 48)

        if (kt < NKT - 2) {
            const int par_empty = (kt >> 1) & 1;          // this kt's phase of empty[s]
            MBARRIER_WAIT_PARITY(sb + SM_BAR_EMPTY + s * 8, par_empty);
            fill_stage(s, (kt + 2) * BK);
        }
    }

    // ---- fused LSTM epilogue (warp-private accumulators; no sync needed) ----
    float* h_out = out;
    float* c_out = out + (size_t)8192 * 1024;

#pragma unroll
    for (int mt = 0; mt < 2; mt++) {
#pragma unroll
        for (int nt = 0; nt < 2; nt++) {
            const int n = n0 + warp_n * 16 + nt * 8 + 2 * t4;
            const float2 bf = *(const float2*)(b_f + n);
            const float2 bi = *(const float2*)(b_i + n);
            const float2 bc = *(const float2*)(b_c + n);
            const float2 bo = *(const float2*)(b_o + n);
#pragma unroll
            for (int rr = 0; rr < 2; rr++) {
                const int m = m0 + warp_m * 32 + mt * 16 + g8 + rr * 8;
                const float2 cp = *(const float2*)(c_prev + (size_t)m * 1024 + n);
                const int i0 = rr * 2, i1 = rr * 2 + 1;

                float2 hv, cv;
                {
                    const float ft = sigmoid_(acc[0][mt][nt][i0] + bf.x);
                    const float it = sigmoid_(acc[1][mt][nt][i0] + bi.x);
                    const float ct = tanh_(acc[2][mt][nt][i0] + bc.x);
                    const float ot = sigmoid_(acc[3][mt][nt][i0] + bo.x);
                    cv.x = ft * cp.x + it * ct;
                    hv.x = ot * tanh_(cv.x);
                }
                {
                    const float ft = sigmoid_(acc[0][mt][nt][i1] + bf.y);
                    const float it = sigmoid_(acc[1][mt][nt][i1] + bi.y);
                    const float ct = tanh_(acc[2][mt][nt][i1] + bc.y);
                    const float ot = sigmoid_(acc[3][mt][nt][i1] + bo.y);
                    cv.y = ft * cp.y + it * ct;
                    hv.y = ot * tanh_(cv.y);
                }
                *(float2*)(h_out + (size_t)m * 1024 + n) = hv;
                *(float2*)(c_out + (size_t)m * 1024 + n) = cv;
            }
        }
    }
}

// ==================== host side ====================

extern "C" void kernel_launch(void* const* d_in, const int* in_sizes, int n_in,
                              void* d_out, int out_size) {
    const float* x      = (const float*)d_in[0];
    const float* h_prev = (const float*)d_in[1];
    const float* c_prev = (const float*)d_in[2];
    const float* W_f = (const float*)d_in[3];
    const float* b_f = (const float*)d_in[4];
    const float* W_i = (const float*)d_in[5];
    const float* b_i = (const float*)d_in[6];
    const float* W_c = (const float*)d_in[7];
    const float* b_c = (const float*)d_in[8];
    const float* W_o = (const float*)d_in[9];
    const float* b_o = (const float*)d_in[10];
    float* out = (float*)d_out;

    cudaFuncSetAttribute(lstm_gemm_kernel,
                         cudaFuncAttributeMaxDynamicSharedMemorySize, SMEM_BYTES);

    conv_all_kernel<<<3072, 256>>>(x, h_prev, W_f, W_i, W_c, W_o);

    dim3 grid(8192 / BM, 1024 / BN);   // (128, 16)
    lstm_gemm_kernel<<<grid, 256, SMEM_BYTES>>>(b_f, b_i, b_c, b_o, c_prev, out);
}